// round 2
// baseline (speedup 1.0000x reference)
#include <cuda_runtime.h>
#include <math.h>

#define HW 1024
#define CC 1024
#define CR 64

typedef unsigned long long ull;

// ---------------- scratch (__device__ globals: no allocation allowed) ----------------
__device__ float g_A[32 * 32];          // row-normalized 1D gaussian, A[i*32+x]
__device__ float g_mean[CC];            // per-channel spatial mean
__device__ float g_scale[CC];           // SE sigmoid scale
__device__ float g_xr[CC * HW];         // sigmoid(x_se), channel-major [c][p]
__device__ float g_xrp[HW * CC];        // sigmoid(x_se), pixel-major [p][c]
__device__ float g_rangeT[HW * CC];     // x_range, pixel-major [p][c]
__device__ float g_spat[CC * HW];       // x_spatial, channel-major [c][p]

// ---------------- 1D gaussian table (separable form of the reference's gus) --------
__global__ void k_init_A() {
    int t = threadIdx.x;          // 1024 threads: warp i handles row i
    int i = t >> 5, x = t & 31;
    float d = (float)(i - x);
    float e = expf(-d * d / 4.5f);   // 2*sigma^2 = 4.5
    float s = e;
    #pragma unroll
    for (int o = 16; o > 0; o >>= 1) s += __shfl_xor_sync(0xffffffffu, s, o);
    g_A[i * 32 + x] = e / s;      // 1/(2*pi*sigma^2) cancels in normalization
}

// ---------------- per-channel spatial mean ----------------
__global__ void k_mean(const float* __restrict__ x) {
    int c = blockIdx.x;
    const float* xc = x + c * HW;
    float s = 0.f;
    for (int i = threadIdx.x; i < HW; i += 256) s += xc[i];
    #pragma unroll
    for (int o = 16; o > 0; o >>= 1) s += __shfl_xor_sync(0xffffffffu, s, o);
    __shared__ float red[8];
    int lane = threadIdx.x & 31, w = threadIdx.x >> 5;
    if (lane == 0) red[w] = s;
    __syncthreads();
    if (threadIdx.x == 0) {
        float t = 0.f;
        #pragma unroll
        for (int i = 0; i < 8; i++) t += red[i];
        g_mean[c] = t * (1.0f / 1024.0f);
    }
}

// ---------------- SE MLP: relu(W1 y + b1) -> sigmoid(W2 h + b2) ----------------
__global__ void k_se(const float* __restrict__ w1, const float* __restrict__ b1,
                     const float* __restrict__ w2, const float* __restrict__ b2) {
    __shared__ float ym[CC];
    __shared__ float h1[CR];
    int t = threadIdx.x;  // 256
    for (int i = t; i < CC; i += 256) ym[i] = g_mean[i];
    __syncthreads();
    {
        int j = t >> 2, l4 = t & 3;
        const float* wr = w1 + j * CC;
        float s = 0.f;
        for (int k = l4; k < CC; k += 4) s += wr[k] * ym[k];
        s += __shfl_xor_sync(0xffffffffu, s, 1);
        s += __shfl_xor_sync(0xffffffffu, s, 2);
        if (l4 == 0) h1[j] = fmaxf(s + b1[j], 0.f);
    }
    __syncthreads();
    for (int c = t; c < CC; c += 256) {
        const float* wr = w2 + c * CR;
        float s = b2[c];
        #pragma unroll
        for (int k = 0; k < CR; k++) s += wr[k] * h1[k];
        g_scale[c] = 1.f / (1.f + expf(-s));
    }
}

// ---------------- per channel: scale, sigmoid (xr), separable gaussian (x_spatial) --
__global__ void k_channel(const float* __restrict__ x) {
    __shared__ float xs[32][33];
    __shared__ float Acol[32][33];  // Acol[y][k] = A[k][y]
    __shared__ float tm[32][33];
    int c = blockIdx.x;
    int t = threadIdx.x;            // 1024 threads
    int r = t >> 5, kk = t & 31;
    float sc = g_scale[c];
    float v = x[c * HW + t] * sc;
    xs[r][kk] = v;                  // xs[h][w]
    g_xr[c * HW + t] = 1.f / (1.f + expf(-v));
    Acol[kk][r] = g_A[t];           // t = k*32+y -> Acol[y][k]
    __syncthreads();
    // tmp[x][k] = sum_y xs[x][y] * A[k][y]
    float s = 0.f;
    #pragma unroll
    for (int y = 0; y < 32; y++) s += xs[r][y] * Acol[y][kk];
    tm[r][kk] = s;
    __syncthreads();
    // out[i][k] = sum_x A[i][x] * tmp[x][k]
    float s2 = 0.f;
    #pragma unroll
    for (int xx = 0; xx < 32; xx++) s2 += Acol[xx][r] * tm[xx][kk];
    g_spat[c * HW + r * 32 + kk] = s2;
}

// ---------------- transpose xr: [c][p] -> [p][c], 32x32 tiles ----------------
__global__ void k_transpose() {
    __shared__ float t[32][33];
    int c0 = blockIdx.y * 32;   // channel tile
    int p0 = blockIdx.x * 32;   // pixel tile
    int tx = threadIdx.x, ty = threadIdx.y;  // 32 x 8
    #pragma unroll
    for (int j = 0; j < 4; j++)
        t[ty + 8 * j][tx] = g_xr[(c0 + ty + 8 * j) * HW + p0 + tx];
    __syncthreads();
    #pragma unroll
    for (int j = 0; j < 4; j++)
        g_xrp[(p0 + ty + 8 * j) * CC + c0 + tx] = t[tx][ty + 8 * j];
}

// ---------------- scrambled 3x3 softmax attention (faithful to reference reshape) ---
// Block p: 9 neighbor rows loaded coalesced into smem, scramble read from smem,
// output written pixel-major (coalesced).
__global__ void k_attn() {
    __shared__ float sn[9][1025];   // stride 1025: bank = (kidx + c2) % 32
    __shared__ float x1s[1024];
    __shared__ float wsum[8][9];
    __shared__ float lg[9];
    __shared__ float attn[9];
    int p = blockIdx.x;
    int py = p >> 5, px = p & 31;
    int t = threadIdx.x;  // 256

    #pragma unroll
    for (int kidx = 0; kidx < 9; kidx++) {
        int sy = py + kidx / 3 - 1;
        int sx = px + kidx % 3 - 1;
        bool valid = ((unsigned)sy < 32u) && ((unsigned)sx < 32u);
        const float* src = g_xrp + (sy * 32 + sx) * CC;
        #pragma unroll
        for (int q = 0; q < 4; q++) {
            int c = t + q * 256;
            sn[kidx][c] = valid ? src[c] : 0.f;
        }
    }
    #pragma unroll
    for (int q = 0; q < 4; q++) x1s[t + q * 256] = g_xrp[p * CC + t + q * 256];
    __syncthreads();

    float pl[9];
    #pragma unroll
    for (int j = 0; j < 9; j++) pl[j] = 0.f;
    float sv[4][9];

    #pragma unroll
    for (int q = 0; q < 4; q++) {
        int cc = t + q * 256;
        float x1v = x1s[cc];
        #pragma unroll
        for (int j = 0; j < 9; j++) {
            int F = j * 1024 + cc;
            int c2 = F / 9;
            int kidx = F - c2 * 9;
            float v = sn[kidx][c2];
            sv[q][j] = v;
            pl[j] += x1v * v;
        }
    }
    int lane = t & 31, w = t >> 5;
    #pragma unroll
    for (int j = 0; j < 9; j++) {
        float s = pl[j];
        #pragma unroll
        for (int o = 16; o > 0; o >>= 1) s += __shfl_xor_sync(0xffffffffu, s, o);
        if (lane == 0) wsum[w][j] = s;
    }
    __syncthreads();
    if (t < 9) {
        float s = 0.f;
        #pragma unroll
        for (int i = 0; i < 8; i++) s += wsum[i][t];
        lg[t] = s;
    }
    __syncthreads();
    if (t == 0) {
        float m = lg[0];
        #pragma unroll
        for (int j = 1; j < 9; j++) m = fmaxf(m, lg[j]);
        float e[9], ss = 0.f;
        #pragma unroll
        for (int j = 0; j < 9; j++) { e[j] = expf(lg[j] - m); ss += e[j]; }
        float inv = 1.f / ss;
        #pragma unroll
        for (int j = 0; j < 9; j++) attn[j] = e[j] * inv;
    }
    __syncthreads();
    float at[9];
    #pragma unroll
    for (int j = 0; j < 9; j++) at[j] = attn[j];
    #pragma unroll
    for (int q = 0; q < 4; q++) {
        int cc = t + q * 256;
        float acc = 0.f;
        #pragma unroll
        for (int j = 0; j < 9; j++) acc += at[j] * sv[q][j];
        g_rangeT[p * CC + cc] = acc;   // coalesced
    }
}

// ---------------- fused 1x1 conv (GEMM 1024x1024x2048, f32x2 packed) + BN + ReLU ----
// BM=128, BN=64, BK=16, 256 threads. Pairs along M (f32x2), B duplicated in smem.
// grid = (16, 8) = 128 blocks.
__device__ __forceinline__ ull ffma2(ull a, ull b, ull c) {
    ull d;
    asm("fma.rn.f32x2 %0, %1, %2, %3;" : "=l"(d) : "l"(a), "l"(b), "l"(c));
    return d;
}

__global__ void k_gemm(const float* __restrict__ Wc,
                       const float* __restrict__ gamma, const float* __restrict__ beta,
                       const float* __restrict__ mean, const float* __restrict__ var,
                       float* __restrict__ out) {
    __shared__ float As[16][130];    // As[k][m], natural M pairs
    __shared__ float Bsd[16][130];   // Bsd[k][2n] = Bsd[k][2n+1] = B[k][n]
    int tid = threadIdx.x;
    int tx = tid & 15, ty = tid >> 4;
    int pcol0 = blockIdx.x * 64;
    int orow0 = blockIdx.y * 128;

    ull acc[4][4];
    #pragma unroll
    for (int i = 0; i < 4; i++)
        #pragma unroll
        for (int j = 0; j < 4; j++) acc[i][j] = 0ull;

    // prefetch addressing
    int am = tid >> 1, ak8 = (tid & 1) * 8;          // A: row m, k-offset
    int brn = tid >> 2, brk4 = (tid & 3) * 4;        // B range: col n, k-offset
    int bsk = tid >> 4, bsn4 = (tid & 15) * 4;       // B spatial: k row, n-offset

    float4 pa0, pa1, pb;
    {
        const float* aw = Wc + (orow0 + am) * 2048 + ak8;
        pa0 = *(const float4*)(aw);
        pa1 = *(const float4*)(aw + 4);
        pb  = *(const float4*)(g_rangeT + (pcol0 + brn) * 1024 + brk4);
    }

    for (int kt = 0; kt < 2048; kt += 16) {
        // store prefetched tile to smem
        {
            const float* a = (const float*)&pa0;
            #pragma unroll
            for (int i = 0; i < 4; i++) As[ak8 + i][am] = a[i];
            const float* b = (const float*)&pa1;
            #pragma unroll
            for (int i = 0; i < 4; i++) As[ak8 + 4 + i][am] = b[i];
            const float* v = (const float*)&pb;
            if (kt < 1024) {
                #pragma unroll
                for (int i = 0; i < 4; i++) {
                    Bsd[brk4 + i][2 * brn]     = v[i];
                    Bsd[brk4 + i][2 * brn + 1] = v[i];
                }
            } else {
                #pragma unroll
                for (int i = 0; i < 4; i++) {
                    Bsd[bsk][2 * (bsn4 + i)]     = v[i];
                    Bsd[bsk][2 * (bsn4 + i) + 1] = v[i];
                }
            }
        }
        __syncthreads();
        // prefetch next tile
        int ktn = kt + 16;
        if (ktn < 2048) {
            const float* aw = Wc + (orow0 + am) * 2048 + ktn + ak8;
            pa0 = *(const float4*)(aw);
            pa1 = *(const float4*)(aw + 4);
            if (ktn < 1024)
                pb = *(const float4*)(g_rangeT + (pcol0 + brn) * 1024 + ktn + brk4);
            else
                pb = *(const float4*)(g_spat + (ktn - 1024 + bsk) * 1024 + pcol0 + bsn4);
        }
        // compute
        #pragma unroll
        for (int k = 0; k < 16; k++) {
            ull av[4], bv[4];
            const ull* pa = (const ull*)&As[k][ty * 8];
            const ull* pbv = (const ull*)&Bsd[k][tx * 8];
            #pragma unroll
            for (int i = 0; i < 4; i++) av[i] = pa[i];
            #pragma unroll
            for (int j = 0; j < 4; j++) bv[j] = pbv[j];
            #pragma unroll
            for (int i = 0; i < 4; i++)
                #pragma unroll
                for (int j = 0; j < 4; j++)
                    acc[i][j] = ffma2(av[i], bv[j], acc[i][j]);
        }
        __syncthreads();
    }

    // epilogue: BN + ReLU
    #pragma unroll
    for (int i = 0; i < 4; i++) {
        int o0 = orow0 + ty * 8 + 2 * i;
        float invg0 = rsqrtf(var[o0] + 1e-5f) * gamma[o0];
        float invg1 = rsqrtf(var[o0 + 1] + 1e-5f) * gamma[o0 + 1];
        float m0 = mean[o0], m1 = mean[o0 + 1];
        float b0 = beta[o0], b1 = beta[o0 + 1];
        #pragma unroll
        for (int j = 0; j < 4; j++) {
            unsigned lo = (unsigned)(acc[i][j] & 0xffffffffull);
            unsigned hi = (unsigned)(acc[i][j] >> 32);
            float v0 = (__uint_as_float(lo) - m0) * invg0 + b0;
            float v1 = (__uint_as_float(hi) - m1) * invg1 + b1;
            int col = pcol0 + tx * 4 + j;
            out[o0 * 1024 + col]       = fmaxf(v0, 0.f);
            out[(o0 + 1) * 1024 + col] = fmaxf(v1, 0.f);
        }
    }
}

extern "C" void kernel_launch(void* const* d_in, const int* in_sizes, int n_in,
                              void* d_out, int out_size) {
    const float* x     = (const float*)d_in[0];
    const float* w1    = (const float*)d_in[1];
    const float* b1    = (const float*)d_in[2];
    const float* w2    = (const float*)d_in[3];
    const float* b2    = (const float*)d_in[4];
    const float* cw    = (const float*)d_in[5];
    const float* gamma = (const float*)d_in[6];
    const float* beta  = (const float*)d_in[7];
    const float* mean  = (const float*)d_in[8];
    const float* var   = (const float*)d_in[9];
    float* out = (float*)d_out;

    k_init_A<<<1, 1024>>>();
    k_mean<<<1024, 256>>>(x);
    k_se<<<1, 256>>>(w1, b1, w2, b2);
    k_channel<<<1024, 1024>>>(x);
    dim3 tg(32, 32);
    dim3 tb(32, 8);
    k_transpose<<<tg, tb>>>();
    k_attn<<<1024, 256>>>();
    dim3 g(16, 8);
    k_gemm<<<g, 256>>>(cw, gamma, beta, mean, var, out);
}

// round 4
// speedup vs baseline: 2.5969x; 2.5969x over previous
#include <cuda_runtime.h>
#include <cuda_bf16.h>
#include <math.h>
#include <stdint.h>

#define HW 1024
#define CC 1024
#define CR 64

// ---------------- scratch ----------------
__device__ float g_A[32 * 32];
__device__ float g_mean[CC];
__device__ float g_scale[CC];
__device__ float g_xr[CC * HW];                 // sigmoid(x_se), channel-major
__device__ float g_xrp[HW * CC];                // sigmoid(x_se), pixel-major
__device__ float g_spat[CC * HW];               // x_spatial, channel-major
__device__ __nv_bfloat16 g_Wh[1024 * 2048];     // conv weight hi/lo bf16 split
__device__ __nv_bfloat16 g_Wl[1024 * 2048];
__device__ __nv_bfloat16 g_Bh[HW * 2048];       // GEMM B hi/lo, K-major [p][k]
__device__ __nv_bfloat16 g_Bl[HW * 2048];

// ---------------- 1D gaussian (separable form of reference's gus) ----------------
__global__ void k_init_A() {
    int t = threadIdx.x;
    int i = t >> 5, x = t & 31;
    float d = (float)(i - x);
    float e = expf(-d * d / 4.5f);
    float s = e;
    #pragma unroll
    for (int o = 16; o > 0; o >>= 1) s += __shfl_xor_sync(0xffffffffu, s, o);
    g_A[i * 32 + x] = e / s;
}

// ---------------- per-channel spatial mean ----------------
__global__ void k_mean(const float* __restrict__ x) {
    int c = blockIdx.x;
    const float* xc = x + c * HW;
    float s = 0.f;
    for (int i = threadIdx.x; i < HW; i += 256) s += xc[i];
    #pragma unroll
    for (int o = 16; o > 0; o >>= 1) s += __shfl_xor_sync(0xffffffffu, s, o);
    __shared__ float red[8];
    int lane = threadIdx.x & 31, w = threadIdx.x >> 5;
    if (lane == 0) red[w] = s;
    __syncthreads();
    if (threadIdx.x == 0) {
        float t = 0.f;
        #pragma unroll
        for (int i = 0; i < 8; i++) t += red[i];
        g_mean[c] = t * (1.0f / 1024.0f);
    }
}

// ---------------- SE MLP ----------------
__global__ void k_se(const float* __restrict__ w1, const float* __restrict__ b1,
                     const float* __restrict__ w2, const float* __restrict__ b2) {
    __shared__ float ym[CC];
    __shared__ float h1[CR];
    int t = threadIdx.x;
    for (int i = t; i < CC; i += 256) ym[i] = g_mean[i];
    __syncthreads();
    {
        int j = t >> 2, l4 = t & 3;
        const float* wr = w1 + j * CC;
        float s = 0.f;
        for (int k = l4; k < CC; k += 4) s += wr[k] * ym[k];
        s += __shfl_xor_sync(0xffffffffu, s, 1);
        s += __shfl_xor_sync(0xffffffffu, s, 2);
        if (l4 == 0) h1[j] = fmaxf(s + b1[j], 0.f);
    }
    __syncthreads();
    for (int c = t; c < CC; c += 256) {
        const float* wr = w2 + c * CR;
        float s = b2[c];
        #pragma unroll
        for (int k = 0; k < CR; k++) s += wr[k] * h1[k];
        g_scale[c] = 1.f / (1.f + expf(-s));
    }
}

// ---------------- split helper ----------------
__device__ __forceinline__ void bsplit(float v, __nv_bfloat16& h, __nv_bfloat16& l) {
    h = __float2bfloat16(v);
    l = __float2bfloat16(v - __bfloat162float(h));
}

// ---------------- W -> hi/lo bf16 ----------------
__global__ void k_convW(const float* __restrict__ w) {
    int base = (blockIdx.x * 256 + threadIdx.x) * 8;
    float4 v0 = *(const float4*)(w + base);
    float4 v1 = *(const float4*)(w + base + 4);
    __nv_bfloat16 h[8], l[8];
    float vv[8] = {v0.x, v0.y, v0.z, v0.w, v1.x, v1.y, v1.z, v1.w};
    #pragma unroll
    for (int i = 0; i < 8; i++) bsplit(vv[i], h[i], l[i]);
    *(uint4*)(g_Wh + base) = *(uint4*)h;
    *(uint4*)(g_Wl + base) = *(uint4*)l;
}

// ---------------- per channel: scale, sigmoid, separable gaussian ----------------
__global__ void k_channel(const float* __restrict__ x) {
    __shared__ float xs[32][33];
    __shared__ float At[32][36];   // At[y][k] = A[k][y]
    __shared__ float tm[32][36];
    int c = blockIdx.x;
    int t = threadIdx.x;           // 256
    float sc = g_scale[c];
    #pragma unroll
    for (int q = 0; q < 4; q++) {
        int p = t + q * 256;
        float v = x[c * HW + p] * sc;
        xs[p >> 5][p & 31] = v;
        g_xr[c * HW + p] = 1.f / (1.f + expf(-v));
    }
    #pragma unroll
    for (int q = 0; q < 4; q++) {
        int i = t + q * 256;       // i = k*32 + y
        At[i & 31][i >> 5] = g_A[i];
    }
    __syncthreads();
    int xrow = t >> 3, k4 = (t & 7) * 4;
    float4 a1 = make_float4(0.f, 0.f, 0.f, 0.f);
    #pragma unroll
    for (int y = 0; y < 32; y++) {
        float xv = xs[xrow][y];
        float4 av = *(const float4*)&At[y][k4];
        a1.x += xv * av.x; a1.y += xv * av.y; a1.z += xv * av.z; a1.w += xv * av.w;
    }
    *(float4*)&tm[xrow][k4] = a1;
    __syncthreads();
    float4 o = make_float4(0.f, 0.f, 0.f, 0.f);
    #pragma unroll
    for (int xx = 0; xx < 32; xx++) {
        float av = At[xx][xrow];
        float4 tv = *(const float4*)&tm[xx][k4];
        o.x += av * tv.x; o.y += av * tv.y; o.z += av * tv.z; o.w += av * tv.w;
    }
    *(float4*)&g_spat[c * HW + xrow * 32 + k4] = o;
}

// ---------------- transposes: xr->xrp (fp32), spat->Bh/Bl (bf16, k>=1024) --------
__global__ void k_transpose() {
    __shared__ float tile[32][33];
    int which = blockIdx.z;
    const float* src = which ? g_spat : g_xr;
    int c0 = blockIdx.y * 32;
    int p0 = blockIdx.x * 32;
    int tx = threadIdx.x, ty = threadIdx.y;  // 32 x 8
    #pragma unroll
    for (int j = 0; j < 4; j++)
        tile[ty + 8 * j][tx] = src[(c0 + ty + 8 * j) * HW + p0 + tx];
    __syncthreads();
    if (which) {
        #pragma unroll
        for (int j = 0; j < 4; j++) {
            float v = tile[tx][ty + 8 * j];
            __nv_bfloat16 h, l;
            bsplit(v, h, l);
            int idx = (p0 + ty + 8 * j) * 2048 + 1024 + c0 + tx;
            g_Bh[idx] = h;
            g_Bl[idx] = l;
        }
    } else {
        #pragma unroll
        for (int j = 0; j < 4; j++)
            g_xrp[(p0 + ty + 8 * j) * CC + c0 + tx] = tile[tx][ty + 8 * j];
    }
}

// ---------------- scrambled 3x3 softmax attention -> Bh/Bl (k<1024) ----------------
__global__ void k_attn() {
    __shared__ float sn[9][1025];
    __shared__ float x1s[1024];
    __shared__ float wsum[8][9];
    __shared__ float lg[9];
    __shared__ float attn[9];
    int p = blockIdx.x;
    int py = p >> 5, px = p & 31;
    int t = threadIdx.x;  // 256

    #pragma unroll
    for (int kidx = 0; kidx < 9; kidx++) {
        int sy = py + kidx / 3 - 1;
        int sx = px + kidx % 3 - 1;
        bool valid = ((unsigned)sy < 32u) && ((unsigned)sx < 32u);
        const float* src = g_xrp + (sy * 32 + sx) * CC;
        #pragma unroll
        for (int q = 0; q < 4; q++) {
            int c = t + q * 256;
            sn[kidx][c] = valid ? src[c] : 0.f;
        }
    }
    #pragma unroll
    for (int q = 0; q < 4; q++) x1s[t + q * 256] = g_xrp[p * CC + t + q * 256];
    __syncthreads();

    float pl[9];
    #pragma unroll
    for (int j = 0; j < 9; j++) pl[j] = 0.f;
    float sv[4][9];
    #pragma unroll
    for (int q = 0; q < 4; q++) {
        int cc = t + q * 256;
        float x1v = x1s[cc];
        #pragma unroll
        for (int j = 0; j < 9; j++) {
            int F = j * 1024 + cc;
            int c2 = F / 9;
            int kidx = F - c2 * 9;
            float v = sn[kidx][c2];
            sv[q][j] = v;
            pl[j] += x1v * v;
        }
    }
    int lane = t & 31, w = t >> 5;
    #pragma unroll
    for (int j = 0; j < 9; j++) {
        float s = pl[j];
        #pragma unroll
        for (int o = 16; o > 0; o >>= 1) s += __shfl_xor_sync(0xffffffffu, s, o);
        if (lane == 0) wsum[w][j] = s;
    }
    __syncthreads();
    if (t < 9) {
        float s = 0.f;
        #pragma unroll
        for (int i = 0; i < 8; i++) s += wsum[i][t];
        lg[t] = s;
    }
    __syncthreads();
    if (t == 0) {
        float m = lg[0];
        #pragma unroll
        for (int j = 1; j < 9; j++) m = fmaxf(m, lg[j]);
        float e[9], ss = 0.f;
        #pragma unroll
        for (int j = 0; j < 9; j++) { e[j] = expf(lg[j] - m); ss += e[j]; }
        float inv = 1.f / ss;
        #pragma unroll
        for (int j = 0; j < 9; j++) attn[j] = e[j] * inv;
    }
    __syncthreads();
    float at[9];
    #pragma unroll
    for (int j = 0; j < 9; j++) at[j] = attn[j];
    #pragma unroll
    for (int q = 0; q < 4; q++) {
        int cc = t + q * 256;
        float acc = 0.f;
        #pragma unroll
        for (int j = 0; j < 9; j++) acc += at[j] * sv[q][j];
        __nv_bfloat16 h, l;
        bsplit(acc, h, l);
        g_Bh[p * 2048 + cc] = h;
        g_Bl[p * 2048 + cc] = l;
    }
}

// =========================== mma.sync bf16-split GEMM ===========================
// D[1024][1024] = W[1024][2048] @ B^T ; CTA tile 128x64, K chunks of 64, 3-stage cp.async.
#define NCHUNK 32
#define SSZ    49152   // Ah 16K | Al 16K | Bh 8K | Bl 8K
#define OFF_AL 16384
#define OFF_BH 32768
#define OFF_BL 40960

__device__ __forceinline__ uint32_t smem_u32(const void* p) {
    uint32_t a;
    asm("{ .reg .u64 t; cvta.to.shared.u64 t, %1; cvt.u32.u64 %0, t; }" : "=r"(a) : "l"(p));
    return a;
}
__device__ __forceinline__ void cp16(uint32_t dst, const void* src) {
    asm volatile("cp.async.ca.shared.global [%0], [%1], 16;" :: "r"(dst), "l"(src) : "memory");
}
__device__ __forceinline__ void ldsm4(uint32_t* r, uint32_t addr) {
    asm volatile("ldmatrix.sync.aligned.m8n8.x4.shared.b16 {%0,%1,%2,%3}, [%4];"
                 : "=r"(r[0]), "=r"(r[1]), "=r"(r[2]), "=r"(r[3]) : "r"(addr));
}
__device__ __forceinline__ void mma16816(float* d, const uint32_t* a, const uint32_t* b) {
    asm volatile(
        "mma.sync.aligned.m16n8k16.row.col.f32.bf16.bf16.f32 "
        "{%0,%1,%2,%3}, {%4,%5,%6,%7}, {%8,%9}, {%0,%1,%2,%3};"
        : "+f"(d[0]), "+f"(d[1]), "+f"(d[2]), "+f"(d[3])
        : "r"(a[0]), "r"(a[1]), "r"(a[2]), "r"(a[3]), "r"(b[0]), "r"(b[1]));
}

// issue one chunk's cp.asyncs (12 x 16B per thread) into stage st
__device__ __forceinline__ void issue_chunk(char* smbase, int st, int ch,
                                            int m0, int n0, int tid) {
    uint32_t sb = smem_u32(smbase + st * SSZ);
    const char* wh = (const char*)g_Wh;
    const char* wl = (const char*)g_Wl;
    const char* bh = (const char*)g_Bh;
    const char* bl = (const char*)g_Bl;
    int kbyte = ch * 128;   // 64 bf16 = 128 bytes per chunk
    #pragma unroll
    for (int q = 0; q < 4; q++) {
        int idx = tid + q * 256;
        int row = idx >> 3, kb = idx & 7;
        int swz = row * 128 + ((kb ^ (row & 7)) << 4);
        long goff = (long)(m0 + row) * 4096 + kbyte + kb * 16;
        cp16(sb + swz,           wh + goff);
        cp16(sb + OFF_AL + swz,  wl + goff);
    }
    #pragma unroll
    for (int q = 0; q < 2; q++) {
        int idx = tid + q * 256;
        int row = idx >> 3, kb = idx & 7;
        int swz = row * 128 + ((kb ^ (row & 7)) << 4);
        long goff = (long)(n0 + row) * 4096 + kbyte + kb * 16;
        cp16(sb + OFF_BH + swz,  bh + goff);
        cp16(sb + OFF_BL + swz,  bl + goff);
    }
    asm volatile("cp.async.commit_group;" ::: "memory");
}

__global__ void __launch_bounds__(256)
k_gemm(const float* __restrict__ gamma, const float* __restrict__ beta,
       const float* __restrict__ mean, const float* __restrict__ var,
       float* __restrict__ out) {
    extern __shared__ char sm[];
    int tid = threadIdx.x;
    int wid = tid >> 5, lane = tid & 31;
    int n0 = blockIdx.x * 64;
    int m0 = blockIdx.y * 128;
    int warp_m = (wid >> 1) * 32;
    int warp_n = (wid & 1) * 32;

    issue_chunk(sm, 0, 0, m0, n0, tid);
    issue_chunk(sm, 1, 1, m0, n0, tid);
    issue_chunk(sm, 2, 2, m0, n0, tid);

    float d[2][4][4];
    #pragma unroll
    for (int i = 0; i < 2; i++)
        #pragma unroll
        for (int j = 0; j < 4; j++)
            #pragma unroll
            for (int q = 0; q < 4; q++) d[i][j][q] = 0.f;

    // per-thread ldmatrix row components
    int a_row_in = (lane & 7) + ((lane >> 3) & 1) * 8;  // 0..15
    int a_kb_off = lane >> 4;                            // 0/1
    int b_sub = lane >> 3;                               // 0..3
    int b_row_in = lane & 7;

    for (int ch = 0; ch < NCHUNK; ch++) {
        int st = ch - (ch / 3) * 3;
        if (ch < NCHUNK - 2)      asm volatile("cp.async.wait_group 2;" ::: "memory");
        else if (ch == NCHUNK - 2) asm volatile("cp.async.wait_group 1;" ::: "memory");
        else                       asm volatile("cp.async.wait_group 0;" ::: "memory");
        __syncthreads();

        uint32_t sb = smem_u32(sm + st * SSZ);
        #pragma unroll
        for (int ks = 0; ks < 4; ks++) {
            uint32_t ah[2][4], al[2][4], bhf[4][2], blf[4][2];
            #pragma unroll
            for (int mt = 0; mt < 2; mt++) {
                int row = warp_m + mt * 16 + a_row_in;
                int kb = 2 * ks + a_kb_off;
                uint32_t ad = sb + row * 128 + ((kb ^ (row & 7)) << 4);
                ldsm4(ah[mt], ad);
                ldsm4(al[mt], ad + OFF_AL);
            }
            #pragma unroll
            for (int q = 0; q < 2; q++) {
                int row = warp_n + (2 * q + (b_sub >> 1)) * 8 + b_row_in;
                int kb = 2 * ks + (b_sub & 1);
                uint32_t bd = sb + OFF_BH + row * 128 + ((kb ^ (row & 7)) << 4);
                uint32_t r[4];
                ldsm4(r, bd);
                bhf[2 * q][0] = r[0]; bhf[2 * q][1] = r[1];
                bhf[2 * q + 1][0] = r[2]; bhf[2 * q + 1][1] = r[3];
                ldsm4(r, bd + (OFF_BL - OFF_BH));
                blf[2 * q][0] = r[0]; blf[2 * q][1] = r[1];
                blf[2 * q + 1][0] = r[2]; blf[2 * q + 1][1] = r[3];
            }
            #pragma unroll
            for (int mt = 0; mt < 2; mt++)
                #pragma unroll
                for (int nt = 0; nt < 4; nt++) {
                    mma16816(d[mt][nt], ah[mt], bhf[nt]);
                    mma16816(d[mt][nt], ah[mt], blf[nt]);
                    mma16816(d[mt][nt], al[mt], bhf[nt]);
                }
        }
        __syncthreads();
        if (ch + 3 < NCHUNK) issue_chunk(sm, st, ch + 3, m0, n0, tid);
    }

    // epilogue: BN + ReLU, float2 stores
    int r4 = lane >> 2, c2 = (lane & 3) * 2;
    #pragma unroll
    for (int mt = 0; mt < 2; mt++) {
        int o0 = m0 + warp_m + mt * 16 + r4;
        int o1 = o0 + 8;
        float i0 = rsqrtf(var[o0] + 1e-5f) * gamma[o0];
        float i1 = rsqrtf(var[o1] + 1e-5f) * gamma[o1];
        float u0 = mean[o0], u1 = mean[o1];
        float t0 = beta[o0], t1 = beta[o1];
        #pragma unroll
        for (int nt = 0; nt < 4; nt++) {
            int col = n0 + warp_n + nt * 8 + c2;
            float2 v0, v1;
            v0.x = fmaxf((d[mt][nt][0] - u0) * i0 + t0, 0.f);
            v0.y = fmaxf((d[mt][nt][1] - u0) * i0 + t0, 0.f);
            v1.x = fmaxf((d[mt][nt][2] - u1) * i1 + t1, 0.f);
            v1.y = fmaxf((d[mt][nt][3] - u1) * i1 + t1, 0.f);
            *(float2*)(out + o0 * 1024 + col) = v0;
            *(float2*)(out + o1 * 1024 + col) = v1;
        }
    }
}

extern "C" void kernel_launch(void* const* d_in, const int* in_sizes, int n_in,
                              void* d_out, int out_size) {
    const float* x     = (const float*)d_in[0];
    const float* w1    = (const float*)d_in[1];
    const float* b1    = (const float*)d_in[2];
    const float* w2    = (const float*)d_in[3];
    const float* b2    = (const float*)d_in[4];
    const float* cw    = (const float*)d_in[5];
    const float* gamma = (const float*)d_in[6];
    const float* beta  = (const float*)d_in[7];
    const float* mean  = (const float*)d_in[8];
    const float* var   = (const float*)d_in[9];
    float* out = (float*)d_out;

    cudaFuncSetAttribute(k_gemm, cudaFuncAttributeMaxDynamicSharedMemorySize, 3 * SSZ);

    k_convW<<<1024, 256>>>(cw);
    k_init_A<<<1, 1024>>>();
    k_mean<<<1024, 256>>>(x);
    k_se<<<1, 256>>>(w1, b1, w2, b2);
    k_channel<<<1024, 256>>>(x);
    k_transpose<<<dim3(32, 32, 2), dim3(32, 8)>>>();
    k_attn<<<1024, 256>>>();
    k_gemm<<<dim3(16, 8), 256, 3 * SSZ>>>(gamma, beta, mean, var, out);
}

// round 5
// speedup vs baseline: 3.8575x; 1.4854x over previous
#include <cuda_runtime.h>
#include <cuda_bf16.h>
#include <math.h>
#include <stdint.h>

#define HW 1024
#define CC 1024
#define CR 64

// ---------------- scratch ----------------
__device__ float g_A[32 * 32];
__device__ float g_mean[CC];
__device__ float g_h1[CR];
__device__ float g_scale[CC];
__device__ float g_xr[CC * HW];                 // sigmoid(x_se), channel-major
__device__ float g_xrp[HW * CC];                // sigmoid(x_se), pixel-major
__device__ float g_spat[CC * HW];               // x_spatial, channel-major
__device__ __nv_bfloat16 g_Wh[1024 * 2048];     // conv weight hi/lo bf16 split
__device__ __nv_bfloat16 g_Wl[1024 * 2048];
__device__ __nv_bfloat16 g_Bh[HW * 2048];       // GEMM B hi/lo, K-major [p][k]
__device__ __nv_bfloat16 g_Bl[HW * 2048];

// ---------------- 1D gaussian (separable form of reference's gus) ----------------
__global__ void k_init_A() {
    int t = threadIdx.x;
    int i = t >> 5, x = t & 31;
    float d = (float)(i - x);
    float e = expf(-d * d / 4.5f);
    float s = e;
    #pragma unroll
    for (int o = 16; o > 0; o >>= 1) s += __shfl_xor_sync(0xffffffffu, s, o);
    g_A[i * 32 + x] = e / s;
}

// ---------------- per-channel spatial mean ----------------
__global__ void k_mean(const float* __restrict__ x) {
    int c = blockIdx.x;
    const float* xc = x + c * HW;
    float s = 0.f;
    for (int i = threadIdx.x; i < HW; i += 256) s += xc[i];
    #pragma unroll
    for (int o = 16; o > 0; o >>= 1) s += __shfl_xor_sync(0xffffffffu, s, o);
    __shared__ float red[8];
    int lane = threadIdx.x & 31, w = threadIdx.x >> 5;
    if (lane == 0) red[w] = s;
    __syncthreads();
    if (threadIdx.x == 0) {
        float t = 0.f;
        #pragma unroll
        for (int i = 0; i < 8; i++) t += red[i];
        g_mean[c] = t * (1.0f / 1024.0f);
    }
}

// ---------------- SE layer 1: h1 = relu(W1 @ mean + b1), 64 blocks ----------------
__global__ void k_se1(const float* __restrict__ w1, const float* __restrict__ b1) {
    int j = blockIdx.x;
    const float* wr = w1 + j * CC;
    float s = 0.f;
    #pragma unroll
    for (int q = 0; q < 4; q++) {
        int k = threadIdx.x + q * 256;
        s += wr[k] * g_mean[k];
    }
    #pragma unroll
    for (int o = 16; o > 0; o >>= 1) s += __shfl_xor_sync(0xffffffffu, s, o);
    __shared__ float red[8];
    int lane = threadIdx.x & 31, w = threadIdx.x >> 5;
    if (lane == 0) red[w] = s;
    __syncthreads();
    if (threadIdx.x == 0) {
        float t = 0.f;
        #pragma unroll
        for (int i = 0; i < 8; i++) t += red[i];
        g_h1[j] = fmaxf(t + b1[j], 0.f);
    }
}

// ---------------- SE layer 2: scale = sigmoid(W2 @ h1 + b2), 32 blocks ----------------
__global__ void k_se2(const float* __restrict__ w2, const float* __restrict__ b2) {
    __shared__ float h1s[CR];
    int t = threadIdx.x;
    if (t < CR) h1s[t] = g_h1[t];
    __syncthreads();
    int gid = blockIdx.x * 256 + t;
    int c = gid >> 3, l8 = gid & 7;
    const float* wr = w2 + c * CR;
    float s = 0.f;
    #pragma unroll
    for (int k = 0; k < 8; k++) s += wr[l8 + k * 8] * h1s[l8 + k * 8];
    s += __shfl_xor_sync(0xffffffffu, s, 1);
    s += __shfl_xor_sync(0xffffffffu, s, 2);
    s += __shfl_xor_sync(0xffffffffu, s, 4);
    if (l8 == 0) g_scale[c] = 1.f / (1.f + expf(-(s + b2[c])));
}

// ---------------- split helper ----------------
__device__ __forceinline__ void bsplit(float v, __nv_bfloat16& h, __nv_bfloat16& l) {
    h = __float2bfloat16(v);
    l = __float2bfloat16(v - __bfloat162float(h));
}

// ---------------- W -> hi/lo bf16 ----------------
__global__ void k_convW(const float* __restrict__ w) {
    int base = (blockIdx.x * 256 + threadIdx.x) * 8;
    float4 v0 = *(const float4*)(w + base);
    float4 v1 = *(const float4*)(w + base + 4);
    __nv_bfloat16 h[8], l[8];
    float vv[8] = {v0.x, v0.y, v0.z, v0.w, v1.x, v1.y, v1.z, v1.w};
    #pragma unroll
    for (int i = 0; i < 8; i++) bsplit(vv[i], h[i], l[i]);
    *(uint4*)(g_Wh + base) = *(uint4*)h;
    *(uint4*)(g_Wl + base) = *(uint4*)l;
}

// ---------------- per channel: scale, sigmoid, separable gaussian ----------------
__global__ void k_channel(const float* __restrict__ x) {
    __shared__ float xs[32][33];
    __shared__ float At[32][36];   // At[y][k] = A[k][y]
    __shared__ float tm[32][36];
    int c = blockIdx.x;
    int t = threadIdx.x;           // 256
    float sc = g_scale[c];
    #pragma unroll
    for (int q = 0; q < 4; q++) {
        int p = t + q * 256;
        float v = x[c * HW + p] * sc;
        xs[p >> 5][p & 31] = v;
        g_xr[c * HW + p] = 1.f / (1.f + expf(-v));
    }
    #pragma unroll
    for (int q = 0; q < 4; q++) {
        int i = t + q * 256;       // i = k*32 + y
        At[i & 31][i >> 5] = g_A[i];
    }
    __syncthreads();
    int xrow = t >> 3, k4 = (t & 7) * 4;
    float4 a1 = make_float4(0.f, 0.f, 0.f, 0.f);
    #pragma unroll
    for (int y = 0; y < 32; y++) {
        float xv = xs[xrow][y];
        float4 av = *(const float4*)&At[y][k4];
        a1.x += xv * av.x; a1.y += xv * av.y; a1.z += xv * av.z; a1.w += xv * av.w;
    }
    *(float4*)&tm[xrow][k4] = a1;
    __syncthreads();
    float4 o = make_float4(0.f, 0.f, 0.f, 0.f);
    #pragma unroll
    for (int xx = 0; xx < 32; xx++) {
        float av = At[xx][xrow];
        float4 tv = *(const float4*)&tm[xx][k4];
        o.x += av * tv.x; o.y += av * tv.y; o.z += av * tv.z; o.w += av * tv.w;
    }
    *(float4*)&g_spat[c * HW + xrow * 32 + k4] = o;
}

// ---------------- transposes: xr->xrp (fp32), spat->Bh/Bl (bf16, k>=1024) --------
__global__ void k_transpose() {
    __shared__ float tile[32][33];
    int which = blockIdx.z;
    const float* src = which ? g_spat : g_xr;
    int c0 = blockIdx.y * 32;
    int p0 = blockIdx.x * 32;
    int tx = threadIdx.x, ty = threadIdx.y;  // 32 x 8
    #pragma unroll
    for (int j = 0; j < 4; j++)
        tile[ty + 8 * j][tx] = src[(c0 + ty + 8 * j) * HW + p0 + tx];
    __syncthreads();
    if (which) {
        #pragma unroll
        for (int j = 0; j < 4; j++) {
            float v = tile[tx][ty + 8 * j];
            __nv_bfloat16 h, l;
            bsplit(v, h, l);
            int idx = (p0 + ty + 8 * j) * 2048 + 1024 + c0 + tx;
            g_Bh[idx] = h;
            g_Bl[idx] = l;
        }
    } else {
        #pragma unroll
        for (int j = 0; j < 4; j++)
            g_xrp[(p0 + ty + 8 * j) * CC + c0 + tx] = tile[tx][ty + 8 * j];
    }
}

// ---------------- scrambled 3x3 softmax attention -> Bh/Bl (k<1024) ----------------
__global__ void k_attn() {
    __shared__ float sn[9][1025];
    __shared__ float x1s[1024];
    __shared__ float wsum[8][9];
    __shared__ float lg[9];
    __shared__ float attn[9];
    int p = blockIdx.x;
    int py = p >> 5, px = p & 31;
    int t = threadIdx.x;  // 256

    #pragma unroll
    for (int kidx = 0; kidx < 9; kidx++) {
        int sy = py + kidx / 3 - 1;
        int sx = px + kidx % 3 - 1;
        bool valid = ((unsigned)sy < 32u) && ((unsigned)sx < 32u);
        const float* src = g_xrp + (sy * 32 + sx) * CC;
        #pragma unroll
        for (int q = 0; q < 4; q++) {
            int c = t + q * 256;
            sn[kidx][c] = valid ? src[c] : 0.f;
        }
    }
    #pragma unroll
    for (int q = 0; q < 4; q++) x1s[t + q * 256] = g_xrp[p * CC + t + q * 256];
    __syncthreads();

    float pl[9];
    #pragma unroll
    for (int j = 0; j < 9; j++) pl[j] = 0.f;
    float sv[4][9];
    #pragma unroll
    for (int q = 0; q < 4; q++) {
        int cc = t + q * 256;
        float x1v = x1s[cc];
        #pragma unroll
        for (int j = 0; j < 9; j++) {
            int F = j * 1024 + cc;
            int c2 = F / 9;
            int kidx = F - c2 * 9;
            float v = sn[kidx][c2];
            sv[q][j] = v;
            pl[j] += x1v * v;
        }
    }
    int lane = t & 31, w = t >> 5;
    #pragma unroll
    for (int j = 0; j < 9; j++) {
        float s = pl[j];
        #pragma unroll
        for (int o = 16; o > 0; o >>= 1) s += __shfl_xor_sync(0xffffffffu, s, o);
        if (lane == 0) wsum[w][j] = s;
    }
    __syncthreads();
    if (t < 9) {
        float s = 0.f;
        #pragma unroll
        for (int i = 0; i < 8; i++) s += wsum[i][t];
        lg[t] = s;
    }
    __syncthreads();
    if (t == 0) {
        float m = lg[0];
        #pragma unroll
        for (int j = 1; j < 9; j++) m = fmaxf(m, lg[j]);
        float e[9], ss = 0.f;
        #pragma unroll
        for (int j = 0; j < 9; j++) { e[j] = expf(lg[j] - m); ss += e[j]; }
        float inv = 1.f / ss;
        #pragma unroll
        for (int j = 0; j < 9; j++) attn[j] = e[j] * inv;
    }
    __syncthreads();
    float at[9];
    #pragma unroll
    for (int j = 0; j < 9; j++) at[j] = attn[j];
    #pragma unroll
    for (int q = 0; q < 4; q++) {
        int cc = t + q * 256;
        float acc = 0.f;
        #pragma unroll
        for (int j = 0; j < 9; j++) acc += at[j] * sv[q][j];
        __nv_bfloat16 h, l;
        bsplit(acc, h, l);
        g_Bh[p * 2048 + cc] = h;
        g_Bl[p * 2048 + cc] = l;
    }
}

// =========================== mma.sync bf16-split GEMM ===========================
// D[1024][1024] = W[1024][2048] @ B^T ; CTA tile 128x64, K chunks of 64, 3-stage cp.async.
#define NCHUNK 32
#define SSZ    49152   // Ah 16K | Al 16K | Bh 8K | Bl 8K
#define OFF_AL 16384
#define OFF_BH 32768
#define OFF_BL 40960

__device__ __forceinline__ uint32_t smem_u32(const void* p) {
    uint32_t a;
    asm("{ .reg .u64 t; cvta.to.shared.u64 t, %1; cvt.u32.u64 %0, t; }" : "=r"(a) : "l"(p));
    return a;
}
__device__ __forceinline__ void cp16(uint32_t dst, const void* src) {
    asm volatile("cp.async.ca.shared.global [%0], [%1], 16;" :: "r"(dst), "l"(src) : "memory");
}
__device__ __forceinline__ void ldsm4(uint32_t* r, uint32_t addr) {
    asm volatile("ldmatrix.sync.aligned.m8n8.x4.shared.b16 {%0,%1,%2,%3}, [%4];"
                 : "=r"(r[0]), "=r"(r[1]), "=r"(r[2]), "=r"(r[3]) : "r"(addr));
}
__device__ __forceinline__ void mma16816(float* d, const uint32_t* a, const uint32_t* b) {
    asm volatile(
        "mma.sync.aligned.m16n8k16.row.col.f32.bf16.bf16.f32 "
        "{%0,%1,%2,%3}, {%4,%5,%6,%7}, {%8,%9}, {%0,%1,%2,%3};"
        : "+f"(d[0]), "+f"(d[1]), "+f"(d[2]), "+f"(d[3])
        : "r"(a[0]), "r"(a[1]), "r"(a[2]), "r"(a[3]), "r"(b[0]), "r"(b[1]));
}

// issue one chunk's cp.asyncs (12 x 16B per thread) into stage st
__device__ __forceinline__ void issue_chunk(char* smbase, int st, int ch,
                                            int m0, int n0, int tid) {
    uint32_t sb = smem_u32(smbase + st * SSZ);
    const char* wh = (const char*)g_Wh;
    const char* wl = (const char*)g_Wl;
    const char* bh = (const char*)g_Bh;
    const char* bl = (const char*)g_Bl;
    int kbyte = ch * 128;   // 64 bf16 = 128 bytes per chunk
    #pragma unroll
    for (int q = 0; q < 4; q++) {
        int idx = tid + q * 256;
        int row = idx >> 3, kb = idx & 7;
        int swz = row * 128 + ((kb ^ (row & 7)) << 4);
        long goff = (long)(m0 + row) * 4096 + kbyte + kb * 16;
        cp16(sb + swz,           wh + goff);
        cp16(sb + OFF_AL + swz,  wl + goff);
    }
    #pragma unroll
    for (int q = 0; q < 2; q++) {
        int idx = tid + q * 256;
        int row = idx >> 3, kb = idx & 7;
        int swz = row * 128 + ((kb ^ (row & 7)) << 4);
        long goff = (long)(n0 + row) * 4096 + kbyte + kb * 16;
        cp16(sb + OFF_BH + swz,  bh + goff);
        cp16(sb + OFF_BL + swz,  bl + goff);
    }
    asm volatile("cp.async.commit_group;" ::: "memory");
}

__global__ void __launch_bounds__(256)
k_gemm(const float* __restrict__ gamma, const float* __restrict__ beta,
       const float* __restrict__ mean, const float* __restrict__ var,
       float* __restrict__ out) {
    extern __shared__ char sm[];
    int tid = threadIdx.x;
    int wid = tid >> 5, lane = tid & 31;
    int n0 = blockIdx.x * 64;
    int m0 = blockIdx.y * 128;
    int warp_m = (wid >> 1) * 32;
    int warp_n = (wid & 1) * 32;

    issue_chunk(sm, 0, 0, m0, n0, tid);
    issue_chunk(sm, 1, 1, m0, n0, tid);
    issue_chunk(sm, 2, 2, m0, n0, tid);

    float d[2][4][4];
    #pragma unroll
    for (int i = 0; i < 2; i++)
        #pragma unroll
        for (int j = 0; j < 4; j++)
            #pragma unroll
            for (int q = 0; q < 4; q++) d[i][j][q] = 0.f;

    // per-thread ldmatrix row components
    int a_row_in = (lane & 7) + ((lane >> 3) & 1) * 8;  // 0..15
    int a_kb_off = lane >> 4;                            // 0/1
    int b_sub = lane >> 3;                               // 0..3
    int b_row_in = lane & 7;

    for (int ch = 0; ch < NCHUNK; ch++) {
        int st = ch - (ch / 3) * 3;
        if (ch < NCHUNK - 2)      asm volatile("cp.async.wait_group 2;" ::: "memory");
        else if (ch == NCHUNK - 2) asm volatile("cp.async.wait_group 1;" ::: "memory");
        else                       asm volatile("cp.async.wait_group 0;" ::: "memory");
        __syncthreads();

        uint32_t sb = smem_u32(sm + st * SSZ);
        #pragma unroll
        for (int ks = 0; ks < 4; ks++) {
            uint32_t ah[2][4], al[2][4], bhf[4][2], blf[4][2];
            #pragma unroll
            for (int mt = 0; mt < 2; mt++) {
                int row = warp_m + mt * 16 + a_row_in;
                int kb = 2 * ks + a_kb_off;
                uint32_t ad = sb + row * 128 + ((kb ^ (row & 7)) << 4);
                ldsm4(ah[mt], ad);
                ldsm4(al[mt], ad + OFF_AL);
            }
            #pragma unroll
            for (int q = 0; q < 2; q++) {
                int row = warp_n + (2 * q + (b_sub >> 1)) * 8 + b_row_in;
                int kb = 2 * ks + (b_sub & 1);
                uint32_t bd = sb + OFF_BH + row * 128 + ((kb ^ (row & 7)) << 4);
                uint32_t r[4];
                ldsm4(r, bd);
                bhf[2 * q][0] = r[0]; bhf[2 * q][1] = r[1];
                bhf[2 * q + 1][0] = r[2]; bhf[2 * q + 1][1] = r[3];
                ldsm4(r, bd + (OFF_BL - OFF_BH));
                blf[2 * q][0] = r[0]; blf[2 * q][1] = r[1];
                blf[2 * q + 1][0] = r[2]; blf[2 * q + 1][1] = r[3];
            }
            #pragma unroll
            for (int mt = 0; mt < 2; mt++)
                #pragma unroll
                for (int nt = 0; nt < 4; nt++) {
                    mma16816(d[mt][nt], ah[mt], bhf[nt]);
                    mma16816(d[mt][nt], ah[mt], blf[nt]);
                    mma16816(d[mt][nt], al[mt], bhf[nt]);
                }
        }
        __syncthreads();
        if (ch + 3 < NCHUNK) issue_chunk(sm, st, ch + 3, m0, n0, tid);
    }

    // epilogue: BN + ReLU, float2 stores
    int r4 = lane >> 2, c2 = (lane & 3) * 2;
    #pragma unroll
    for (int mt = 0; mt < 2; mt++) {
        int o0 = m0 + warp_m + mt * 16 + r4;
        int o1 = o0 + 8;
        float i0 = rsqrtf(var[o0] + 1e-5f) * gamma[o0];
        float i1 = rsqrtf(var[o1] + 1e-5f) * gamma[o1];
        float u0 = mean[o0], u1 = mean[o1];
        float t0 = beta[o0], t1 = beta[o1];
        #pragma unroll
        for (int nt = 0; nt < 4; nt++) {
            int col = n0 + warp_n + nt * 8 + c2;
            float2 v0, v1;
            v0.x = fmaxf((d[mt][nt][0] - u0) * i0 + t0, 0.f);
            v0.y = fmaxf((d[mt][nt][1] - u0) * i0 + t0, 0.f);
            v1.x = fmaxf((d[mt][nt][2] - u1) * i1 + t1, 0.f);
            v1.y = fmaxf((d[mt][nt][3] - u1) * i1 + t1, 0.f);
            *(float2*)(out + o0 * 1024 + col) = v0;
            *(float2*)(out + o1 * 1024 + col) = v1;
        }
    }
}

extern "C" void kernel_launch(void* const* d_in, const int* in_sizes, int n_in,
                              void* d_out, int out_size) {
    const float* x     = (const float*)d_in[0];
    const float* w1    = (const float*)d_in[1];
    const float* b1    = (const float*)d_in[2];
    const float* w2    = (const float*)d_in[3];
    const float* b2    = (const float*)d_in[4];
    const float* cw    = (const float*)d_in[5];
    const float* gamma = (const float*)d_in[6];
    const float* beta  = (const float*)d_in[7];
    const float* mean  = (const float*)d_in[8];
    const float* var   = (const float*)d_in[9];
    float* out = (float*)d_out;

    cudaFuncSetAttribute(k_gemm, cudaFuncAttributeMaxDynamicSharedMemorySize, 3 * SSZ);

    k_convW<<<1024, 256>>>(cw);
    k_init_A<<<1, 1024>>>();
    k_mean<<<1024, 256>>>(x);
    k_se1<<<64, 256>>>(w1, b1);
    k_se2<<<32, 256>>>(w2, b2);
    k_channel<<<1024, 256>>>(x);
    k_transpose<<<dim3(32, 32, 2), dim3(32, 8)>>>();
    k_attn<<<1024, 256>>>();
    k_gemm<<<dim3(16, 8), 256, 3 * SSZ>>>(gamma, beta, mean, var, out);
}